// round 1
// baseline (speedup 1.0000x reference)
#include <cuda_runtime.h>
#include <cstdint>

// InversePixelShuffle (pixel_unshuffle, k=2)
// in : (B=8, C=32, H=512, W=512) fp32
// out: (B=8, C*4=128, Ho=256, Wo=256) fp32
// out[b, c*4 + y*2 + x, ho, wo] = in[b, c, 2*ho + y, 2*wo + x]
//
// Strategy: input-driven streaming. Each thread loads one float4 (4
// consecutive input floats along W). Even-w elements (v.x, v.z) form a
// contiguous float2 in output channel co = c*4 + 2*y; odd-w elements
// (v.y, v.w) form a contiguous float2 in channel co+1, at the same
// (ho, wo/2) position. Both loads and stores are fully coalesced.

static constexpr unsigned W4_PER_ROW = 512 / 4;   // 128 float4 per input row
static constexpr unsigned H          = 512;
static constexpr unsigned TOTAL_F4   = 8u * 32u * 512u * 512u / 4u;  // 16,777,216
static constexpr unsigned OUT_CH_STRIDE_F2 = 256u * 128u;            // 256*256 floats / 2

__global__ void __launch_bounds__(256)
inverse_pixel_shuffle_kernel(const float4* __restrict__ in,
                             float2* __restrict__ out) {
    unsigned tid = blockIdx.x * blockDim.x + threadIdx.x;

    // Decompose tid (float4 index) into (bc, h, w4) — all power-of-2 shifts.
    unsigned w4   = tid & (W4_PER_ROW - 1);     // position along W in float4 units
    unsigned rest = tid >> 7;                   // b*32*512 + c*512 + h
    unsigned h    = rest & (H - 1);
    unsigned bc   = rest >> 9;                  // b*32 + c

    float4 v = in[tid];

    unsigned ho = h >> 1;
    unsigned y  = h & 1;
    // co includes batch: (b*32 + c)*4 = b*128 + c*4
    unsigned co = bc * 4u + y * 2u;

    // float2 index of out[b, co, ho, wo] with wo = w4*2:
    // ((co*256 + ho)*256 + wo) / 2 = (co*256 + ho)*128 + w4
    size_t base = ((size_t)co * 256u + ho) * 128u + w4;

    out[base]                     = make_float2(v.x, v.z);  // channel co   (x = 0)
    out[base + OUT_CH_STRIDE_F2]  = make_float2(v.y, v.w);  // channel co+1 (x = 1)
}

extern "C" void kernel_launch(void* const* d_in, const int* in_sizes, int n_in,
                              void* d_out, int out_size) {
    const float4* in  = (const float4*)d_in[0];
    float2*       out = (float2*)d_out;

    const unsigned threads = 256;
    const unsigned blocks  = TOTAL_F4 / threads;  // 65536
    inverse_pixel_shuffle_kernel<<<blocks, threads>>>(in, out);
}

// round 2
// speedup vs baseline: 1.0031x; 1.0031x over previous
#include <cuda_runtime.h>
#include <cstdint>

// InversePixelShuffle (pixel_unshuffle, k=2)
// in : (B=8, C=32, H=512, W=512) fp32
// out: (B=8, 128, 256, 256) fp32
// out[b, c*4 + y*2 + x, ho, wo] = in[b, c, 2*ho + y, 2*wo + x]
//
// Warp-per-input-row layout:
//   warp wid <-> (bc, h); lane l loads float4 pairs (2l, 2l+1) and
//   (64+2l, 65+2l) of the row. A consecutive float4 pair deinterleaves
//   into one float4 of even-w elements (channel co = bc*4 + 2y) and one
//   float4 of odd-w elements (channel co+1), both at output row ho = h/2.
//   Store instructions are perfectly lane-contiguous (512B/warp each).
//   Loads are stride-32B 16B accesses; the sibling load in the same warp
//   covers the complementary sectors, so DRAM still reads each line once.

static constexpr unsigned H_IN        = 512;
static constexpr unsigned F4_PER_ROW  = 512 / 4;          // 128
static constexpr unsigned NUM_ROWS    = 8u * 32u * 512u;  // 131072 warps
static constexpr unsigned OUT_CH_F4   = 256u * 256u / 4u; // 16384
static constexpr unsigned OUT_ROW_F4  = 256u / 4u;        // 64

__global__ void __launch_bounds__(256)
inverse_pixel_shuffle_kernel(const float4* __restrict__ in,
                             float4* __restrict__ out) {
    unsigned tid  = blockIdx.x * blockDim.x + threadIdx.x;
    unsigned lane = tid & 31u;
    unsigned wid  = tid >> 5;                 // one warp per input row

    unsigned h  = wid & (H_IN - 1);
    unsigned bc = wid >> 9;                   // b*32 + c

    const float4* inrow = in + ((size_t)wid << 7);   // wid * 128 float4

    // Four independent loads (MLP=4). Pairs (a0,a1) and (b0,b1) are
    // consecutive float4 -> 8 consecutive input floats each.
    float4 a0 = inrow[2u * lane];
    float4 a1 = inrow[2u * lane + 1u];
    float4 b0 = inrow[64u + 2u * lane];
    float4 b1 = inrow[64u + 2u * lane + 1u];

    unsigned ho = h >> 1;
    unsigned y  = h & 1u;
    unsigned co = bc * 4u + y * 2u;           // includes batch: b*128 + c*4 + 2y

    float4* orow = out + ((size_t)co * 256u + ho) * OUT_ROW_F4;

    // Even-w elements -> channel co
    orow[lane]                      = make_float4(a0.x, a0.z, a1.x, a1.z);
    orow[32u + lane]                = make_float4(b0.x, b0.z, b1.x, b1.z);
    // Odd-w elements -> channel co+1
    orow[OUT_CH_F4 + lane]          = make_float4(a0.y, a0.w, a1.y, a1.w);
    orow[OUT_CH_F4 + 32u + lane]    = make_float4(b0.y, b0.w, b1.y, b1.w);
}

extern "C" void kernel_launch(void* const* d_in, const int* in_sizes, int n_in,
                              void* d_out, int out_size) {
    const float4* in  = (const float4*)d_in[0];
    float4*       out = (float4*)d_out;

    const unsigned threads = 256;                         // 8 warps = 8 rows/block
    const unsigned blocks  = (NUM_ROWS * 32u) / threads;  // 16384
    inverse_pixel_shuffle_kernel<<<blocks, threads>>>(in, out);
}

// round 3
// speedup vs baseline: 1.0047x; 1.0016x over previous
#include <cuda_runtime.h>
#include <cstdint>

// InversePixelShuffle (pixel_unshuffle, k=2)
// in : (B=8, C=32, H=512, W=512) fp32
// out: (B=8, 128, 256, 256) fp32
// out[b, c*4 + y*2 + x, ho, wo] = in[b, c, 2*ho + y, 2*wo + x]
//
// Warp-per-h-pair layout (MLP_p1 = 8):
//   warp wid <-> (bc, ho). It reads input rows h0 = 2*ho and h1 = 2*ho+1
//   (256 float4 contiguous) and writes one 256-float row in each of the four
//   output channels co = bc*4 .. bc*4+3:
//     row h0 even-w -> co+0, row h0 odd-w -> co+1,
//     row h1 even-w -> co+2, row h1 odd-w -> co+3.
//   Lane l loads float4 pairs (2l,2l+1) and (64+2l,65+2l) from each row:
//   8 independent front-batched LDG.128, then 8 lane-contiguous STG.128
//   (512B per warp per store instruction). Sibling loads in the same warp
//   cover complementary 16B half-sectors, so DRAM reads each line once.

static constexpr unsigned NUM_WARPS  = 8u * 32u * 256u;   // (b*c) * ho = 65536
static constexpr unsigned OUT_CH_F4  = 256u * 256u / 4u;  // 16384
static constexpr unsigned OUT_ROW_F4 = 256u / 4u;         // 64

__global__ void __launch_bounds__(256)
inverse_pixel_shuffle_kernel(const float4* __restrict__ in,
                             float4* __restrict__ out) {
    unsigned tid  = blockIdx.x * blockDim.x + threadIdx.x;
    unsigned lane = tid & 31u;
    unsigned wid  = tid >> 5;

    unsigned ho = wid & 255u;
    unsigned bc = wid >> 8;                   // b*32 + c

    // Input rows 2*ho and 2*ho+1 of image bc: float4 offset
    // (bc*512 + 2*ho)*128 = wid*256.
    const float4* r0 = in + ((size_t)wid << 8);
    const float4* r1 = r0 + 128;

    unsigned l2 = 2u * lane;

    // 8 independent loads, front-batched (MLP_p1 = 8).
    float4 a0 = r0[l2];        float4 a1 = r0[l2 + 1u];
    float4 b0 = r0[64u + l2];  float4 b1 = r0[64u + l2 + 1u];
    float4 c0 = r1[l2];        float4 c1 = r1[l2 + 1u];
    float4 d0 = r1[64u + l2];  float4 d1 = r1[64u + l2 + 1u];

    unsigned co = bc * 4u;                    // b*128 + c*4
    float4* o = out + ((size_t)co * 256u + ho) * OUT_ROW_F4;

    // channel co+0: row h0, even w
    o[lane]                         = make_float4(a0.x, a0.z, a1.x, a1.z);
    o[32u + lane]                   = make_float4(b0.x, b0.z, b1.x, b1.z);
    // channel co+1: row h0, odd w
    o[OUT_CH_F4 + lane]             = make_float4(a0.y, a0.w, a1.y, a1.w);
    o[OUT_CH_F4 + 32u + lane]       = make_float4(b0.y, b0.w, b1.y, b1.w);
    // channel co+2: row h1, even w
    o[2u * OUT_CH_F4 + lane]        = make_float4(c0.x, c0.z, c1.x, c1.z);
    o[2u * OUT_CH_F4 + 32u + lane]  = make_float4(d0.x, d0.z, d1.x, d1.z);
    // channel co+3: row h1, odd w
    o[3u * OUT_CH_F4 + lane]        = make_float4(c0.y, c0.w, c1.y, c1.w);
    o[3u * OUT_CH_F4 + 32u + lane]  = make_float4(d0.y, d0.w, d1.y, d1.w);
}

extern "C" void kernel_launch(void* const* d_in, const int* in_sizes, int n_in,
                              void* d_out, int out_size) {
    const float4* in  = (const float4*)d_in[0];
    float4*       out = (float4*)d_out;

    const unsigned threads = 256;                          // 8 warps/block
    const unsigned blocks  = (NUM_WARPS * 32u) / threads;  // 8192
    inverse_pixel_shuffle_kernel<<<blocks, threads>>>(in, out);
}